// round 16
// baseline (speedup 1.0000x reference)
#include <cuda_runtime.h>

#define BB 16
#define LL 48000
#define WW 64
#define LWT 512
#define BL (BB*LL)

#define NC0 3000      // 48000/16 level-0 chunks per row
#define NCH (BB*NC0)  // all level-0 chunks
#define NR1 188       // ceil(3000/16)
#define NP1 3008      // 3000 padded
#define NR2 12        // ceil(188/16)

#define L0_BLOCKS ((NCH + 255) / 256)          // 188
#define PW_BLOCKS ((WW * LWT + 255) / 256)     // 128

// Static device scratch (no allocation).
__device__ float g_s0[BL];           // level-0 inner sequential 16-scans
__device__ float g_t0[BB][NC0];      // level-0 chunk sums
__device__ float g_o0[BB][NC0];      // final exclusive offsets per level-0 chunk
__device__ float g_wtT[LWT * WW];    // wavetables transposed to (LWT, W)

// Fused: level-0 sequential 16-scans (reduce_window eval order) + wavetable transpose.
__global__ __launch_bounds__(256) void seq_level0(const float* __restrict__ pitch,
                                                  const float* __restrict__ wt) {
    if (blockIdx.x >= L0_BLOCKS) {
        int i = (blockIdx.x - L0_BLOCKS) * blockDim.x + threadIdx.x;
        if (i < WW * LWT) {
            int w = i >> 9;
            int p = i & (LWT - 1);
            g_wtT[p * WW + w] = wt[i];
        }
        return;
    }
    int c = blockIdx.x * blockDim.x + threadIdx.x;    // global chunk id
    if (c >= NCH) return;
    const float4* p4 = (const float4*)(pitch + c * 16);
    float o[16];
    float s = 0.0f;                                   // init; 0+x0 exact
#pragma unroll
    for (int q = 0; q < 4; q++) {
        float4 v = __ldg(&p4[q]);
        s = __fadd_rn(s, __fmul_rn(0.032f, v.x)); o[q*4+0] = s;
        s = __fadd_rn(s, __fmul_rn(0.032f, v.y)); o[q*4+1] = s;
        s = __fadd_rn(s, __fmul_rn(0.032f, v.z)); o[q*4+2] = s;
        s = __fadd_rn(s, __fmul_rn(0.032f, v.w)); o[q*4+3] = s;
    }
    float4* d4 = (float4*)(g_s0 + c * 16);
#pragma unroll
    for (int q = 0; q < 4; q++)
        d4[q] = make_float4(o[q*4+0], o[q*4+1], o[q*4+2], o[q*4+3]);
    g_t0[c / NC0][c % NC0] = s;
}

// Levels 1..3 per batch row: ReduceWindowRewriter recursion with sequential inner scans.
__global__ __launch_bounds__(256) void seq_upper(void) {
    __shared__ float t0s[NP1];
    __shared__ float s1[NP1];
    __shared__ float s2[NR2 * 16];
    __shared__ float sc12[NR2];

    int b = blockIdx.x;
    int tid = threadIdx.x, nt = blockDim.x;

    for (int j = tid; j < NP1; j += nt)
        t0s[j] = (j < NC0) ? g_t0[b][j] : 0.0f;
    __syncthreads();

    for (int k = tid; k < NR1; k += nt) {
        float s = 0.0f;
#pragma unroll
        for (int j = 0; j < 16; j++) {
            s = __fadd_rn(s, t0s[k * 16 + j]);
            s1[k * 16 + j] = s;
        }
    }
    __syncthreads();

    for (int k = tid; k < NR2; k += nt) {
        float s = 0.0f;
#pragma unroll
        for (int j = 0; j < 16; j++) {
            int r = k * 16 + j;
            float v = (r < NR1) ? s1[r * 16 + 15] : 0.0f;
            s = __fadd_rn(s, v);
            s2[r] = s;
        }
    }
    __syncthreads();

    if (tid == 0) {
        float s = 0.0f;
#pragma unroll
        for (int k = 0; k < NR2; k++) {
            s = __fadd_rn(s, s2[k * 16 + 15]);
            sc12[k] = s;
        }
    }
    __syncthreads();

    for (int c = tid; c < NC0; c += nt) {
        float o;
        if (c == 0) o = 0.0f;
        else {
            int j = c - 1;
            float v = s1[j];
            if (j >= 16) {
                int k = (j >> 4) - 1;
                float sk = s2[k];
                if (k >= 16) sk = __fadd_rn(sc12[(k >> 4) - 1], sk);
                o = __fadd_rn(sk, v);
            } else o = v;
        }
        g_o0[b][c] = o;
    }
}

// Synth: warp covers 8 consecutive elements. Fully-coalesced attention reads
// (f4 index f = q*32+lane => element 2q+(lane>>4)); each half-warp spans one
// element's full 256B wavetable row per gather instruction. Index math fused:
// lanes 0..7 compute one element each (bit-identical to R4 path), shfl-broadcast.
__global__ __launch_bounds__(256) void synth(const float* __restrict__ pitch,
                                             const float* __restrict__ env,
                                             const float* __restrict__ attn,
                                             float* __restrict__ out) {
    unsigned warp = threadIdx.x >> 5;
    unsigned lane = threadIdx.x & 31u;
    unsigned eb = blockIdx.x * 64u + warp * 8u;   // first element of this warp

    // index math for element eb+lane (lanes 0..7 only)
    float alpha = 0.0f;
    unsigned ilih = 0u;
    if (lane < 8u) {
        unsigned e = eb + lane;
        unsigned b = e / LL;                       // const divisor -> mulhi
        unsigned l = e - b * LL;
        float cum = __fadd_rn(g_o0[b][l >> 4], g_s0[e]);
        float r = __fsub_rn(cum, __fmul_rn(0.032f, pitch[l]));  // ref subtracts row-0 increment
        r = fmodf(r, 512.0f);                      // lax.rem (exact)
        if (r < 0.0f) r += 512.0f;                 // jnp.remainder sign fix
        if (512.0f - r < 1e-5f) r = 0.0f;          // the where() fixup
        float lowf = floorf(r);
        alpha = __fsub_rn(r, lowf);                // exact
        int il = (int)lowf;
        int ih = (int)ceilf(r);
        if (ih >= LWT) ih = 0;                     // ceil % 512
        ilih = (unsigned)il | ((unsigned)ih << 16);
    }

    const float4* a4 = (const float4*)attn + (size_t)eb * 16;
    unsigned hw = lane >> 4;                       // half-warp id
    float accL[4], accH[4];
#pragma unroll
    for (int q = 0; q < 4; q++) {
        unsigned f = q * 32 + lane;                // warp-local float4 index (coalesced)
        unsigned ew = 2 * q + hw;                  // element this lane contributes to
        unsigned v = __shfl_sync(0xffffffffu, ilih, ew);
        unsigned w4 = f & 15u;
        float4 a  = __ldg(a4 + f);
        float4 wl = __ldg((const float4*)g_wtT + (v & 0xffffu) * 16 + w4);
        float4 wh = __ldg((const float4*)g_wtT + (v >> 16) * 16 + w4);
        accL[q] = a.x * wl.x + a.y * wl.y + a.z * wl.z + a.w * wl.w;
        accH[q] = a.x * wh.x + a.y * wh.y + a.z * wh.z + a.w * wh.w;
    }

    // reduce within each half-warp (xor offsets < 16 stay inside the half-warp)
#pragma unroll
    for (int q = 0; q < 4; q++) {
#pragma unroll
        for (int o = 1; o < 16; o <<= 1) {
            accL[q] += __shfl_xor_sync(0xffffffffu, accL[q], o);
            accH[q] += __shfl_xor_sync(0xffffffffu, accH[q], o);
        }
    }

    // epilogue: lane (hw*16 + q) finishes element 2q+hw.
    // Alpha broadcast is CONVERGENT (all 32 lanes execute the shfl each q);
    // only the writer lanes consume it. (Divergent shfl here was the R8 bug.)
#pragma unroll
    for (int q = 0; q < 4; q++) {
        unsigned ew = 2 * q + hw;
        float al = __shfl_sync(0xffffffffu, alpha, ew);
        if ((lane & 15u) == (unsigned)q) {
            unsigned e = eb + ew;
            float s = accL[q] + al * (accH[q] - accL[q]);
            out[e] = s * __ldg(&env[e]);
        }
    }
}

extern "C" void kernel_launch(void* const* d_in, const int* in_sizes, int n_in,
                              void* d_out, int out_size) {
    const float* pitch = (const float*)d_in[0];
    const float* env   = (const float*)d_in[1];
    const float* attn  = (const float*)d_in[2];
    const float* wt    = (const float*)d_in[3];
    float* out = (float*)d_out;

    seq_level0<<<L0_BLOCKS + PW_BLOCKS, 256>>>(pitch, wt);
    seq_upper<<<BB, 256>>>();
    synth<<<BL / 64, 256>>>(pitch, env, attn, out);   // 12000 blocks, warp per 8 elements
}